// round 15
// baseline (speedup 1.0000x reference)
#include <cuda_runtime.h>
#include <cuda_bf16.h>
#include <cuda_fp8.h>
#include <cstdint>

// ---------------------------------------------------------------------------
// TransformerV2: conv feature branch + patch-similarity top-5 attention.
// Shapes fixed: B=1, Cin=64, Cq=32, H=W=96, L=9216, D=32*9=288.
// R13: similarity GEMM in fp8 e4m3 (mma.sync m16n8k32, baseline PTX) —
//      half the mma instructions of bf16 k16. 64 candidates/query with
//      exact fp32 rescore. Single barrier/tile, double-buffered scores.
//      Convs: measured R10 kernels.
// ---------------------------------------------------------------------------

#define Hh 96
#define Ww 96
#define HW 9216
#define CIN 64
#define CQ  32
#define DQ  288
#define LQ  9216

typedef unsigned long long ull;

// -------------------------- scratch (static, no allocs) --------------------
__device__ float g_t1  [CIN * HW];
__device__ float g_feat[CIN * HW];
__device__ float g_q   [CQ  * HW];
__device__ float g_k   [CQ  * HW];
__device__ float g_Qn  [LQ * DQ];          // fp32 normalized (exact rescore)
__device__ float g_Kn  [LQ * DQ];
__device__ uint8_t g_Qn8[LQ * DQ];         // e4m3 (16 * normalized)
__device__ uint8_t g_Kn8[LQ * DQ];
__device__ float g_xT  [HW * CIN];
__device__ float g_tv  [LQ * 5];
__device__ int   g_ti  [LQ * 5];

// ======================= PTX helpers (compute_103-safe) ====================
__device__ __forceinline__ uint32_t smem_u32(const void* p) {
    uint32_t a;
    asm("{ .reg .u64 t; cvta.to.shared.u64 t, %1; cvt.u32.u64 %0, t; }"
        : "=r"(a) : "l"(p));
    return a;
}
__device__ __forceinline__ void cp16(uint32_t dst, const void* src) {
    asm volatile("cp.async.cg.shared.global [%0], [%1], 16;"
                 :: "r"(dst), "l"(src) : "memory");
}
#define CP_COMMIT() asm volatile("cp.async.commit_group;" ::: "memory")
#define CP_WAIT0()  asm volatile("cp.async.wait_group 0;" ::: "memory")

__device__ __forceinline__ void ldsm4(uint32_t* r, uint32_t addr) {
    asm volatile("ldmatrix.sync.aligned.m8n8.x4.shared.b16 {%0,%1,%2,%3}, [%4];"
                 : "=r"(r[0]), "=r"(r[1]), "=r"(r[2]), "=r"(r[3]) : "r"(addr));
}
// fp8 e4m3 mma: m16n8k32, f32 accum. A frag 4 regs, B frag 2 regs.
__device__ __forceinline__ void mma_fp8(float* d, const uint32_t* a,
                                        const uint32_t* b) {
    asm volatile(
        "mma.sync.aligned.m16n8k32.row.col.f32.e4m3.e4m3.f32 "
        "{%0,%1,%2,%3}, {%4,%5,%6,%7}, {%8,%9}, {%0,%1,%2,%3};"
        : "+f"(d[0]), "+f"(d[1]), "+f"(d[2]), "+f"(d[3])
        : "r"(a[0]), "r"(a[1]), "r"(a[2]), "r"(a[3]), "r"(b[0]), "r"(b[1]));
}

// ---------------------------------------------------------------------------
// 3x3 SAME conv (R10 version — measured; 4 outs/block, pipelined).
// ---------------------------------------------------------------------------
template<int RPT>
__global__ void __launch_bounds__(256) conv3x3_t(
    const float* __restrict__ in,
    const float* __restrict__ wgt,
    const float* __restrict__ bias,
    float* __restrict__ out,
    int doRelu)
{
    constexpr int TH = 8 * RPT;
    constexpr int TL = (TH + 2) * 34;
    constexpr int NP = (TL + 255) / 256;

    __shared__ float tin[2][TH + 2][36];
    __shared__ float wsm[64][36];

    const int tx = threadIdx.x;
    const int ty = threadIdx.y;
    const int tid = ty * 32 + tx;
    const int x0 = blockIdx.x * 32;
    const int y0 = blockIdx.y * TH;
    const int og = blockIdx.z * 4;

    for (int i = tid; i < 4 * 64 * 9; i += 256) {
        int o = i / 576, rem = i - o * 576, ci = rem / 9, k = rem - ci * 9;
        wsm[ci][o * 9 + k] = wgt[((og + o) * 64 + ci) * 9 + k];
    }

    float pf[NP];
#pragma unroll
    for (int j = 0; j < NP; j++) {
        int i = tid + j * 256;
        float v = 0.f;
        if (i < TL) {
            int r = i / 34, c = i - r * 34;
            int gy = y0 - 1 + r, gx = x0 - 1 + c;
            if (gy >= 0 && gy < Hh && gx >= 0 && gx < Ww)
                v = in[gy * Ww + gx];
        }
        pf[j] = v;
    }

    float acc[4][RPT];
#pragma unroll
    for (int o = 0; o < 4; o++)
#pragma unroll
        for (int rr = 0; rr < RPT; rr++) acc[o][rr] = 0.f;

    for (int ci = 0; ci < 64; ci++) {
        const int buf = ci & 1;
#pragma unroll
        for (int j = 0; j < NP; j++) {
            int i = tid + j * 256;
            if (i < TL) {
                int r = i / 34, c = i - r * 34;
                tin[buf][r][c] = pf[j];
            }
        }
        __syncthreads();

        if (ci < 63) {
            const float* p = in + (ci + 1) * HW;
#pragma unroll
            for (int j = 0; j < NP; j++) {
                int i = tid + j * 256;
                float v = 0.f;
                if (i < TL) {
                    int r = i / 34, c = i - r * 34;
                    int gy = y0 - 1 + r, gx = x0 - 1 + c;
                    if (gy >= 0 && gy < Hh && gx >= 0 && gx < Ww)
                        v = p[gy * Ww + gx];
                }
                pf[j] = v;
            }
        }

        float v[RPT][9];
#pragma unroll
        for (int rr = 0; rr < RPT; rr++) {
            int yl = ty + 8 * rr;
#pragma unroll
            for (int dy = 0; dy < 3; dy++)
#pragma unroll
                for (int dx = 0; dx < 3; dx++)
                    v[rr][dy * 3 + dx] = tin[buf][yl + dy][tx + dx];
        }
#pragma unroll
        for (int o = 0; o < 4; o++) {
            float w9[9];
#pragma unroll
            for (int k = 0; k < 9; k++) w9[k] = wsm[ci][o * 9 + k];
#pragma unroll
            for (int rr = 0; rr < RPT; rr++)
#pragma unroll
                for (int k = 0; k < 9; k++)
                    acc[o][rr] = fmaf(v[rr][k], w9[k], acc[o][rr]);
        }
    }

    const int gx = x0 + tx;
#pragma unroll
    for (int o = 0; o < 4; o++) {
        float b = bias[og + o];
#pragma unroll
        for (int rr = 0; rr < RPT; rr++) {
            int gy = y0 + ty + 8 * rr;
            float r = acc[o][rr] + b;
            if (doRelu) r = fmaxf(r, 0.f);
            out[(og + o) * HW + gy * Ww + gx] = r;
        }
    }
}

// ---------------------------------------------------------------------------
// L2-normalized 3x3 patch vectors, fp32 + e4m3(x16) outputs.
// q and k in one launch: blockIdx.y = 0 -> q, 1 -> k. grid (9216,2), blk 288.
// ---------------------------------------------------------------------------
__global__ void patch_norm_kernel(
    const float* __restrict__ fq, const float* __restrict__ fk,
    float* __restrict__ vq, uint8_t* __restrict__ vq8,
    float* __restrict__ vk, uint8_t* __restrict__ vk8)
{
    const float* f = blockIdx.y ? fk : fq;
    float* vec = blockIdx.y ? vk : vq;
    uint8_t* vec8 = blockIdx.y ? vk8 : vq8;

    const int l = blockIdx.x;
    const int y = l / Ww, x = l - y * Ww;
    const int d = threadIdx.x;
    const int c = d / 9, ij = d - c * 9;
    const int dy = ij / 3 - 1, dx = ij % 3 - 1;
    const int yy = y + dy, xx = x + dx;

    float v = 0.f;
    if (yy >= 0 && yy < Hh && xx >= 0 && xx < Ww)
        v = f[c * HW + yy * Ww + xx];

    __shared__ float red[9];
    __shared__ float nrm;
    float s = v * v;
#pragma unroll
    for (int off = 16; off > 0; off >>= 1)
        s += __shfl_down_sync(0xffffffffu, s, off);
    if ((d & 31) == 0) red[d >> 5] = s;
    __syncthreads();
    if (d == 0) {
        float t = 0.f;
#pragma unroll
        for (int i = 0; i < 9; i++) t += red[i];
        nrm = fmaxf(sqrtf(t), 1e-12f);
    }
    __syncthreads();
    float o = v / nrm;
    vec[l * DQ + d] = o;
    vec8[l * DQ + d] =
        (uint8_t)__nv_cvt_float_to_fp8(o * 16.f, __NV_SATFINITE, __NV_E4M3);
}

// ---------------------------------------------------------------------------
__global__ void transpose_x_kernel(const float* __restrict__ x,
                                   float* __restrict__ xT)
{
    int i = blockIdx.x * 256 + threadIdx.x;
    if (i < CIN * HW) {
        int p = i >> 6, c = i & 63;
        xT[i] = x[c * HW + p];
    }
}

// ---------------------------------------------------------------------------
// fp8 mma similarity + streaming top-16/span + exact fp32 rescore.
// CTA: 64 queries, 72 key tiles of 128, K=288 fp8 (9 k-steps of 32B).
// 8 warps; warp w: keys [(w&3)*32,+32) x queries [(w>>2)*32,+32).
// A double-buffered (cp.async), scores double-buffered -> ONE barrier/tile.
// A/B rows 288B, stride 304B (19x16B, odd -> conflict-free ldmatrix).
// grid 144, block 256, dynamic smem 164864 B.
// ---------------------------------------------------------------------------
#define ASTRB  304
#define ABUF   (128 * ASTRB)                // 38912 per A buffer
#define SMB_B  (2 * ABUF)                   // 77824
#define SMB_SC (SMB_B + 64 * ASTRB)         // 97280
#define SCTILE (128 * 66)                   // floats per score buffer
#define SIM_SMEM (SMB_SC + 2 * SCTILE * 4)  // 164864

#define NCAND 64                            // 16 per span * 4 spans
struct SimCand { float v[64][NCAND]; int id[64][NCAND]; };

__global__ void __launch_bounds__(256, 1) sim_top5_fp8(
    const uint8_t* __restrict__ Kn8,
    const uint8_t* __restrict__ Qn8,
    const float* __restrict__ Kn,
    const float* __restrict__ Qn,
    float* __restrict__ tvals,
    int*   __restrict__ tidx)
{
    extern __shared__ __align__(16) char dynsm[];
    const uint32_t smb = smem_u32(dynsm);
    float* scoresAll = (float*)(dynsm + SMB_SC);
    SimCand* cand = (SimCand*)(dynsm + SMB_SC);   // aliases score buf 0 (+1)

    const int tid  = threadIdx.x;
    const int lane = tid & 31;
    const int wid  = tid >> 5;
    const int qBase = blockIdx.x * 64;

    const int wK = (wid & 3) * 32;
    const int wQ = (wid >> 2) * 32;

    const int sRow = tid >> 1, sHalf = tid & 1;   // staging: 2 thr/row, 144B ea

    // ---- stage B (64 queries x 288B) once + preload A tile 0 ----
    if (tid < 128) {
        const uint8_t* src = Qn8 + (size_t)(qBase + sRow) * DQ + sHalf * 144;
        uint32_t dst = smb + SMB_B + sRow * ASTRB + sHalf * 144;
#pragma unroll
        for (int j = 0; j < 9; j++) cp16(dst + j * 16, src + j * 16);
    }
    {
        const uint8_t* src = Kn8 + (size_t)sRow * DQ + sHalf * 144;
        uint32_t dst = smb + sRow * ASTRB + sHalf * 144;
#pragma unroll
        for (int j = 0; j < 9; j++) cp16(dst + j * 16, src + j * 16);
    }
    CP_COMMIT();
    CP_WAIT0();
    __syncthreads();

    // ldmatrix byte offsets (same frag trick as bf16: 32 fp8 = 16 b16)
    const uint32_t aOff0 = (uint32_t)(wK + (lane & 15)) * ASTRB
                         + ((lane >> 4) & 1) * 16;
    const uint32_t aOff1 = aOff0 + 16 * ASTRB;
    const uint32_t bByte = smb + SMB_B
        + (uint32_t)(wQ + ((lane >> 4) & 1) * 8 + (lane & 7)) * ASTRB
        + ((lane >> 3) & 1) * 16;

    float vtop[16]; int itop[16];
#pragma unroll
    for (int r = 0; r < 16; r++) { vtop[r] = -1e30f; itop[r] = 0; }
    const int qScan = tid & 63, span = tid >> 6;

    for (int kt = 0; kt < 72; kt++) {
        // prefetch next A tile (overlaps GEMM)
        if (kt < 71) {
            const uint8_t* src =
                Kn8 + (size_t)((kt + 1) * 128 + sRow) * DQ + sHalf * 144;
            uint32_t dst = smb + (uint32_t)((kt + 1) & 1) * ABUF
                         + sRow * ASTRB + sHalf * 144;
#pragma unroll
            for (int j = 0; j < 9; j++) cp16(dst + j * 16, src + j * 16);
            CP_COMMIT();
        }

        // ---- 32x32 warp-tile GEMM, K=288 fp8 (9 steps of 32B) ----
        float acc[8][4];
#pragma unroll
        for (int f = 0; f < 8; f++)
#pragma unroll
            for (int e = 0; e < 4; e++) acc[f][e] = 0.f;

        const uint32_t aBuf = smb + (uint32_t)(kt & 1) * ABUF;
#pragma unroll
        for (int ks = 0; ks < 9; ks++) {
            const uint32_t kb = ks * 32;
            uint32_t a0[4], a1[4], b0[4], b1[4];
            ldsm4(a0, aBuf + aOff0 + kb);
            ldsm4(a1, aBuf + aOff1 + kb);
            ldsm4(b0, bByte + kb);               // n 0-15 of warp
            ldsm4(b1, bByte + 16 * ASTRB + kb);  // n 16-31 of warp
            mma_fp8(acc[0], a0, b0);     mma_fp8(acc[4], a1, b0);
            mma_fp8(acc[1], a0, b0 + 2); mma_fp8(acc[5], a1, b0 + 2);
            mma_fp8(acc[2], a0, b1);     mma_fp8(acc[6], a1, b1);
            mma_fp8(acc[3], a0, b1 + 2); mma_fp8(acc[7], a1, b1 + 2);
        }

        // ---- D frags -> scores[key][query] (double-buffered) ----
        float* sc = scoresAll + (kt & 1) * SCTILE;
#pragma unroll
        for (int mi = 0; mi < 2; mi++)
#pragma unroll
            for (int ni = 0; ni < 4; ni++) {
                const float* d = acc[mi * 4 + ni];
                int row = wK + mi * 16 + (lane >> 2);
                int col = wQ + ni * 8 + (lane & 3) * 2;
                *(float2*)&sc[row * 66 + col] = make_float2(d[0], d[1]);
                *(float2*)&sc[(row + 8) * 66 + col] = make_float2(d[2], d[3]);
            }
        if (kt < 71) CP_WAIT0();
        __syncthreads();     // the ONLY barrier per tile

        // ---- scan this tile's scores (overlaps next GEMM issue) ----
        {
            const float* col = sc + (span * 32) * 66 + qScan;
            const int gBase = kt * 128 + span * 32;
            for (int i = 0; i < 32; i++) {
                float v = col[i * 66];
                if (v > vtop[15]) {
                    vtop[15] = v; itop[15] = gBase + i;
#pragma unroll
                    for (int r = 15; r > 0; r--)
                        if (vtop[r] > vtop[r - 1]) {
                            float tv = vtop[r - 1]; vtop[r - 1] = vtop[r]; vtop[r] = tv;
                            int ti = itop[r - 1]; itop[r - 1] = itop[r]; itop[r] = ti;
                        }
                }
            }
        }
    }
    __syncthreads();   // all scans done before cand aliases score buffers

    // ---- candidates -> smem ----
#pragma unroll
    for (int r = 0; r < 16; r++) {
        cand->v [qScan][span * 16 + r] = vtop[r];
        cand->id[qScan][span * 16 + r] = itop[r];
    }
    __syncthreads();

    // ---- exact fp32 rescore: 16 candidates per thread ----
    {
        const float4* qr = (const float4*)(Qn + (size_t)(qBase + qScan) * DQ);
        int ids[16];
#pragma unroll
        for (int j = 0; j < 16; j++) ids[j] = cand->id[qScan][span * 16 + j];
#pragma unroll 2
        for (int j = 0; j < 16; j++) {
            const float4* kr = (const float4*)(Kn + (size_t)ids[j] * DQ);
            float s = 0.f;
#pragma unroll 4
            for (int t = 0; t < 72; t++) {
                float4 a = qr[t], b = kr[t];
                s += a.x * b.x; s += a.y * b.y; s += a.z * b.z; s += a.w * b.w;
            }
            cand->v[qScan][span * 16 + j] = s;
        }
    }
    __syncthreads();

    // ---- final top-5 selection (tie -> lower index) ----
    if (tid < 64) {
        int q = tid;
        for (int r = 0; r < 5; r++) {
            float best = -1e30f; int bi = 0x7fffffff; int bj = 0;
            for (int j = 0; j < NCAND; j++) {
                float v = cand->v[q][j]; int id = cand->id[q][j];
                if (v > best || (v == best && id < bi)) { best = v; bi = id; bj = j; }
            }
            tvals[(qBase + q) * 5 + r] = best;
            tidx [(qBase + q) * 5 + r] = bi;
            cand->v[q][bj] = -1e31f;
        }
    }
}

// ---------------------------------------------------------------------------
__global__ void assemble_kernel(const float* __restrict__ x,
                                const float* __restrict__ xT,
                                const float* __restrict__ feat,
                                const float* __restrict__ tvals,
                                const int*   __restrict__ tidx,
                                float* __restrict__ out)
{
    const int tid = threadIdx.x;
    const int pix = blockIdx.x * 4 + (tid >> 6);
    const int c = tid & 63;
    const int Y = pix / Ww, X = pix - Y * Ww;

    float s = 0.f;
#pragma unroll
    for (int r = 1; r < 5; r++) {
        float S = tvals[pix * 5 + r];
        float inner = 0.f;
#pragma unroll
        for (int dy = -1; dy <= 1; dy++) {
            int ly = Y + dy;
            if (ly < 0 || ly >= Hh) continue;
#pragma unroll
            for (int dx = -1; dx <= 1; dx++) {
                int lx = X + dx;
                if (lx < 0 || lx >= Ww) continue;
                int m = tidx[(ly * Ww + lx) * 5 + r];
                int my = m / Ww, mx = m - my * Ww;
                int sy = my - dy, sx = mx - dx;
                if (sy >= 0 && sy < Hh && sx >= 0 && sx < Ww)
                    inner += xT[(sy * Ww + sx) * CIN + c];
            }
        }
        s += S * inner;
    }
    out[c * HW + pix] = feat[c * HW + pix] + x[c * HW + pix] + s * (1.0f / 36.0f);
}

// ---------------------------------------------------------------------------
extern "C" void kernel_launch(void* const* d_in, const int* in_sizes, int n_in,
                              void* d_out, int out_size)
{
    (void)in_sizes; (void)n_in; (void)out_size;
    const float* x  = (const float*)d_in[0];
    const float* W1 = (const float*)d_in[1];
    const float* b1 = (const float*)d_in[2];
    const float* W2 = (const float*)d_in[3];
    const float* b2 = (const float*)d_in[4];
    const float* Wq = (const float*)d_in[5];
    const float* bq = (const float*)d_in[6];
    const float* Wk = (const float*)d_in[7];
    const float* bk = (const float*)d_in[8];
    float* out = (float*)d_out;

    float *t1, *feat, *qb, *kb, *Qn, *Kn, *xT, *tv;
    uint8_t *Qn8, *Kn8;
    int* ti;
    cudaGetSymbolAddress((void**)&t1,   g_t1);
    cudaGetSymbolAddress((void**)&feat, g_feat);
    cudaGetSymbolAddress((void**)&qb,   g_q);
    cudaGetSymbolAddress((void**)&kb,   g_k);
    cudaGetSymbolAddress((void**)&Qn,   g_Qn);
    cudaGetSymbolAddress((void**)&Kn,   g_Kn);
    cudaGetSymbolAddress((void**)&Qn8,  g_Qn8);
    cudaGetSymbolAddress((void**)&Kn8,  g_Kn8);
    cudaGetSymbolAddress((void**)&xT,   g_xT);
    cudaGetSymbolAddress((void**)&tv,   g_tv);
    cudaGetSymbolAddress((void**)&ti,   g_ti);

    cudaFuncSetAttribute(sim_top5_fp8,
                         cudaFuncAttributeMaxDynamicSharedMemorySize, SIM_SMEM);

    dim3 cblk(32, 8);
    conv3x3_t<2><<<dim3(3, 6, 16), cblk>>>(x,  W1, b1, t1,   1);
    conv3x3_t<2><<<dim3(3, 6, 16), cblk>>>(t1, W2, b2, feat, 1);
    conv3x3_t<1><<<dim3(3, 12, 8), cblk>>>(x,  Wq, bq, qb,   0);
    conv3x3_t<1><<<dim3(3, 12, 8), cblk>>>(x,  Wk, bk, kb,   0);

    patch_norm_kernel<<<dim3(LQ, 2), DQ>>>(qb, kb, Qn, Qn8, Kn, Kn8);
    transpose_x_kernel<<<(CIN * HW + 255) / 256, 256>>>(x, xT);

    sim_top5_fp8<<<144, 256, SIM_SMEM>>>(Kn8, Qn8, Kn, Qn, tv, ti);

    assemble_kernel<<<HW / 4, 256>>>(x, xT, feat, tv, ti, out);
}

// round 16
// speedup vs baseline: 1.0060x; 1.0060x over previous
#include <cuda_runtime.h>
#include <cuda_bf16.h>
#include <cstdint>

// ---------------------------------------------------------------------------
// TransformerV2: conv feature branch + patch-similarity top-5 attention.
// Shapes fixed: B=1, Cin=64, Cq=32, H=W=96, L=9216, D=32*9=288.
// R15: similarity GEMM in int8 IMMA (mma.sync m16n8k32 s8 -> s32, native
//      Turing-lineage path). Exact integer scores, 48 candidates/query,
//      exact fp32 rescore. Overhead trims vs R13 (no dead cand-v store,
//      register rescore, depth-12 scan). Convs: measured R10 kernels.
// ---------------------------------------------------------------------------

#define Hh 96
#define Ww 96
#define HW 9216
#define CIN 64
#define CQ  32
#define DQ  288
#define LQ  9216

typedef unsigned long long ull;

// -------------------------- scratch (static, no allocs) --------------------
__device__ float g_t1  [CIN * HW];
__device__ float g_feat[CIN * HW];
__device__ float g_q   [CQ  * HW];
__device__ float g_k   [CQ  * HW];
__device__ float g_Qn  [LQ * DQ];          // fp32 normalized (exact rescore)
__device__ float g_Kn  [LQ * DQ];
__device__ uint8_t g_Qn8[LQ * DQ];         // s8 (127 * normalized)
__device__ uint8_t g_Kn8[LQ * DQ];
__device__ float g_xT  [HW * CIN];
__device__ float g_tv  [LQ * 5];
__device__ int   g_ti  [LQ * 5];

// ======================= PTX helpers (compute_103-safe) ====================
__device__ __forceinline__ uint32_t smem_u32(const void* p) {
    uint32_t a;
    asm("{ .reg .u64 t; cvta.to.shared.u64 t, %1; cvt.u32.u64 %0, t; }"
        : "=r"(a) : "l"(p));
    return a;
}
__device__ __forceinline__ void cp16(uint32_t dst, const void* src) {
    asm volatile("cp.async.cg.shared.global [%0], [%1], 16;"
                 :: "r"(dst), "l"(src) : "memory");
}
#define CP_COMMIT() asm volatile("cp.async.commit_group;" ::: "memory")
#define CP_WAIT0()  asm volatile("cp.async.wait_group 0;" ::: "memory")

__device__ __forceinline__ void ldsm4(uint32_t* r, uint32_t addr) {
    asm volatile("ldmatrix.sync.aligned.m8n8.x4.shared.b16 {%0,%1,%2,%3}, [%4];"
                 : "=r"(r[0]), "=r"(r[1]), "=r"(r[2]), "=r"(r[3]) : "r"(addr));
}
// int8 IMMA: m16n8k32, s32 accum. A frag 4 regs, B frag 2 regs.
__device__ __forceinline__ void mma_s8(int* d, const uint32_t* a,
                                       const uint32_t* b) {
    asm volatile(
        "mma.sync.aligned.m16n8k32.row.col.s32.s8.s8.s32 "
        "{%0,%1,%2,%3}, {%4,%5,%6,%7}, {%8,%9}, {%0,%1,%2,%3};"
        : "+r"(d[0]), "+r"(d[1]), "+r"(d[2]), "+r"(d[3])
        : "r"(a[0]), "r"(a[1]), "r"(a[2]), "r"(a[3]), "r"(b[0]), "r"(b[1]));
}

// ---------------------------------------------------------------------------
// 3x3 SAME conv (R10 version — measured; 4 outs/block, pipelined).
// ---------------------------------------------------------------------------
template<int RPT>
__global__ void __launch_bounds__(256) conv3x3_t(
    const float* __restrict__ in,
    const float* __restrict__ wgt,
    const float* __restrict__ bias,
    float* __restrict__ out,
    int doRelu)
{
    constexpr int TH = 8 * RPT;
    constexpr int TL = (TH + 2) * 34;
    constexpr int NP = (TL + 255) / 256;

    __shared__ float tin[2][TH + 2][36];
    __shared__ float wsm[64][36];

    const int tx = threadIdx.x;
    const int ty = threadIdx.y;
    const int tid = ty * 32 + tx;
    const int x0 = blockIdx.x * 32;
    const int y0 = blockIdx.y * TH;
    const int og = blockIdx.z * 4;

    for (int i = tid; i < 4 * 64 * 9; i += 256) {
        int o = i / 576, rem = i - o * 576, ci = rem / 9, k = rem - ci * 9;
        wsm[ci][o * 9 + k] = wgt[((og + o) * 64 + ci) * 9 + k];
    }

    float pf[NP];
#pragma unroll
    for (int j = 0; j < NP; j++) {
        int i = tid + j * 256;
        float v = 0.f;
        if (i < TL) {
            int r = i / 34, c = i - r * 34;
            int gy = y0 - 1 + r, gx = x0 - 1 + c;
            if (gy >= 0 && gy < Hh && gx >= 0 && gx < Ww)
                v = in[gy * Ww + gx];
        }
        pf[j] = v;
    }

    float acc[4][RPT];
#pragma unroll
    for (int o = 0; o < 4; o++)
#pragma unroll
        for (int rr = 0; rr < RPT; rr++) acc[o][rr] = 0.f;

    for (int ci = 0; ci < 64; ci++) {
        const int buf = ci & 1;
#pragma unroll
        for (int j = 0; j < NP; j++) {
            int i = tid + j * 256;
            if (i < TL) {
                int r = i / 34, c = i - r * 34;
                tin[buf][r][c] = pf[j];
            }
        }
        __syncthreads();

        if (ci < 63) {
            const float* p = in + (ci + 1) * HW;
#pragma unroll
            for (int j = 0; j < NP; j++) {
                int i = tid + j * 256;
                float v = 0.f;
                if (i < TL) {
                    int r = i / 34, c = i - r * 34;
                    int gy = y0 - 1 + r, gx = x0 - 1 + c;
                    if (gy >= 0 && gy < Hh && gx >= 0 && gx < Ww)
                        v = p[gy * Ww + gx];
                }
                pf[j] = v;
            }
        }

        float v[RPT][9];
#pragma unroll
        for (int rr = 0; rr < RPT; rr++) {
            int yl = ty + 8 * rr;
#pragma unroll
            for (int dy = 0; dy < 3; dy++)
#pragma unroll
                for (int dx = 0; dx < 3; dx++)
                    v[rr][dy * 3 + dx] = tin[buf][yl + dy][tx + dx];
        }
#pragma unroll
        for (int o = 0; o < 4; o++) {
            float w9[9];
#pragma unroll
            for (int k = 0; k < 9; k++) w9[k] = wsm[ci][o * 9 + k];
#pragma unroll
            for (int rr = 0; rr < RPT; rr++)
#pragma unroll
                for (int k = 0; k < 9; k++)
                    acc[o][rr] = fmaf(v[rr][k], w9[k], acc[o][rr]);
        }
    }

    const int gx = x0 + tx;
#pragma unroll
    for (int o = 0; o < 4; o++) {
        float b = bias[og + o];
#pragma unroll
        for (int rr = 0; rr < RPT; rr++) {
            int gy = y0 + ty + 8 * rr;
            float r = acc[o][rr] + b;
            if (doRelu) r = fmaxf(r, 0.f);
            out[(og + o) * HW + gy * Ww + gx] = r;
        }
    }
}

// ---------------------------------------------------------------------------
// L2-normalized 3x3 patch vectors, fp32 + s8(x127) outputs.
// q and k in one launch: blockIdx.y = 0 -> q, 1 -> k. grid (9216,2), blk 288.
// ---------------------------------------------------------------------------
__global__ void patch_norm_kernel(
    const float* __restrict__ fq, const float* __restrict__ fk,
    float* __restrict__ vq, uint8_t* __restrict__ vq8,
    float* __restrict__ vk, uint8_t* __restrict__ vk8)
{
    const float* f = blockIdx.y ? fk : fq;
    float* vec = blockIdx.y ? vk : vq;
    uint8_t* vec8 = blockIdx.y ? vk8 : vq8;

    const int l = blockIdx.x;
    const int y = l / Ww, x = l - y * Ww;
    const int d = threadIdx.x;
    const int c = d / 9, ij = d - c * 9;
    const int dy = ij / 3 - 1, dx = ij % 3 - 1;
    const int yy = y + dy, xx = x + dx;

    float v = 0.f;
    if (yy >= 0 && yy < Hh && xx >= 0 && xx < Ww)
        v = f[c * HW + yy * Ww + xx];

    __shared__ float red[9];
    __shared__ float nrm;
    float s = v * v;
#pragma unroll
    for (int off = 16; off > 0; off >>= 1)
        s += __shfl_down_sync(0xffffffffu, s, off);
    if ((d & 31) == 0) red[d >> 5] = s;
    __syncthreads();
    if (d == 0) {
        float t = 0.f;
#pragma unroll
        for (int i = 0; i < 9; i++) t += red[i];
        nrm = fmaxf(sqrtf(t), 1e-12f);
    }
    __syncthreads();
    float o = v / nrm;
    vec[l * DQ + d] = o;
    int qi = __float2int_rn(o * 127.f);
    qi = max(-127, min(127, qi));
    vec8[l * DQ + d] = (uint8_t)(signed char)qi;
}

// ---------------------------------------------------------------------------
__global__ void transpose_x_kernel(const float* __restrict__ x,
                                   float* __restrict__ xT)
{
    int i = blockIdx.x * 256 + threadIdx.x;
    if (i < CIN * HW) {
        int p = i >> 6, c = i & 63;
        xT[i] = x[c * HW + p];
    }
}

// ---------------------------------------------------------------------------
// int8 IMMA similarity + streaming top-12/span + exact fp32 rescore.
// CTA: 64 queries, 72 key tiles of 128, K=288 s8 (9 k-steps of 32B).
// 8 warps; warp w: keys [(w&3)*32,+32) x queries [(w>>2)*32,+32).
// A double-buffered (cp.async), scores double-buffered -> ONE barrier/tile.
// A/B rows 288B, stride 304B (19x16B, odd -> conflict-free ldmatrix).
// grid 144, block 256, dynamic smem 164864 B.
// ---------------------------------------------------------------------------
#define ASTRB  304
#define ABUF   (128 * ASTRB)                // 38912 per A buffer
#define SMB_B  (2 * ABUF)                   // 77824
#define SMB_SC (SMB_B + 64 * ASTRB)         // 97280
#define SCTILE (128 * 66)                   // ints per score buffer
#define SIM_SMEM (SMB_SC + 2 * SCTILE * 4)  // 164864

#define TOPS  12                            // streaming top-k per span
#define NCAND 48                            // 12 per span * 4 spans
struct SimCand { float v[64][NCAND]; int id[64][NCAND]; };

__global__ void __launch_bounds__(256, 1) sim_top5_s8(
    const uint8_t* __restrict__ Kn8,
    const uint8_t* __restrict__ Qn8,
    const float* __restrict__ Kn,
    const float* __restrict__ Qn,
    float* __restrict__ tvals,
    int*   __restrict__ tidx)
{
    extern __shared__ __align__(16) char dynsm[];
    const uint32_t smb = smem_u32(dynsm);
    int* scoresAll = (int*)(dynsm + SMB_SC);
    SimCand* cand = (SimCand*)(dynsm + SMB_SC);   // aliases score buffers

    const int tid  = threadIdx.x;
    const int lane = tid & 31;
    const int wid  = tid >> 5;
    const int qBase = blockIdx.x * 64;

    const int wK = (wid & 3) * 32;
    const int wQ = (wid >> 2) * 32;

    const int sRow = tid >> 1, sHalf = tid & 1;   // staging: 2 thr/row, 144B ea

    // ---- stage B (64 queries x 288B) once + preload A tile 0 ----
    if (tid < 128) {
        const uint8_t* src = Qn8 + (size_t)(qBase + sRow) * DQ + sHalf * 144;
        uint32_t dst = smb + SMB_B + sRow * ASTRB + sHalf * 144;
#pragma unroll
        for (int j = 0; j < 9; j++) cp16(dst + j * 16, src + j * 16);
    }
    {
        const uint8_t* src = Kn8 + (size_t)sRow * DQ + sHalf * 144;
        uint32_t dst = smb + sRow * ASTRB + sHalf * 144;
#pragma unroll
        for (int j = 0; j < 9; j++) cp16(dst + j * 16, src + j * 16);
    }
    CP_COMMIT();
    CP_WAIT0();
    __syncthreads();

    // ldmatrix byte offsets (8-bit k32 frag = same addressing as b16 k16)
    const uint32_t aOff0 = (uint32_t)(wK + (lane & 15)) * ASTRB
                         + ((lane >> 4) & 1) * 16;
    const uint32_t aOff1 = aOff0 + 16 * ASTRB;
    const uint32_t bByte = smb + SMB_B
        + (uint32_t)(wQ + ((lane >> 4) & 1) * 8 + (lane & 7)) * ASTRB
        + ((lane >> 3) & 1) * 16;

    int vtop[TOPS]; int itop[TOPS];
#pragma unroll
    for (int r = 0; r < TOPS; r++) { vtop[r] = -0x7fffffff; itop[r] = 0; }
    const int qScan = tid & 63, span = tid >> 6;

    for (int kt = 0; kt < 72; kt++) {
        // prefetch next A tile (overlaps GEMM)
        if (kt < 71) {
            const uint8_t* src =
                Kn8 + (size_t)((kt + 1) * 128 + sRow) * DQ + sHalf * 144;
            uint32_t dst = smb + (uint32_t)((kt + 1) & 1) * ABUF
                         + sRow * ASTRB + sHalf * 144;
#pragma unroll
            for (int j = 0; j < 9; j++) cp16(dst + j * 16, src + j * 16);
            CP_COMMIT();
        }

        // ---- 32x32 warp-tile GEMM, K=288 s8 (9 steps of 32B) ----
        int acc[8][4];
#pragma unroll
        for (int f = 0; f < 8; f++)
#pragma unroll
            for (int e = 0; e < 4; e++) acc[f][e] = 0;

        const uint32_t aBuf = smb + (uint32_t)(kt & 1) * ABUF;
#pragma unroll
        for (int ks = 0; ks < 9; ks++) {
            const uint32_t kb = ks * 32;
            uint32_t a0[4], a1[4], b0[4], b1[4];
            ldsm4(a0, aBuf + aOff0 + kb);
            ldsm4(a1, aBuf + aOff1 + kb);
            ldsm4(b0, bByte + kb);               // n 0-15 of warp
            ldsm4(b1, bByte + 16 * ASTRB + kb);  // n 16-31 of warp
            mma_s8(acc[0], a0, b0);     mma_s8(acc[4], a1, b0);
            mma_s8(acc[1], a0, b0 + 2); mma_s8(acc[5], a1, b0 + 2);
            mma_s8(acc[2], a0, b1);     mma_s8(acc[6], a1, b1);
            mma_s8(acc[3], a0, b1 + 2); mma_s8(acc[7], a1, b1 + 2);
        }

        // ---- D frags -> scores[key][query] (double-buffered) ----
        int* sc = scoresAll + (kt & 1) * SCTILE;
#pragma unroll
        for (int mi = 0; mi < 2; mi++)
#pragma unroll
            for (int ni = 0; ni < 4; ni++) {
                const int* d = acc[mi * 4 + ni];
                int row = wK + mi * 16 + (lane >> 2);
                int col = wQ + ni * 8 + (lane & 3) * 2;
                *(int2*)&sc[row * 66 + col] = make_int2(d[0], d[1]);
                *(int2*)&sc[(row + 8) * 66 + col] = make_int2(d[2], d[3]);
            }
        if (kt < 71) CP_WAIT0();
        __syncthreads();     // the ONLY barrier per tile

        // ---- scan this tile's scores ----
        {
            const int* col = sc + (span * 32) * 66 + qScan;
            const int gBase = kt * 128 + span * 32;
            for (int i = 0; i < 32; i++) {
                int v = col[i * 66];
                if (v > vtop[TOPS - 1]) {
                    vtop[TOPS - 1] = v; itop[TOPS - 1] = gBase + i;
#pragma unroll
                    for (int r = TOPS - 1; r > 0; r--)
                        if (vtop[r] > vtop[r - 1]) {
                            int tv = vtop[r - 1]; vtop[r - 1] = vtop[r]; vtop[r] = tv;
                            int ti = itop[r - 1]; itop[r - 1] = itop[r]; itop[r] = ti;
                        }
                }
            }
        }
    }
    __syncthreads();   // all scans done before cand aliases score buffers

    // ---- exact fp32 rescore straight from registers; write cand ----
    {
        const float4* qr = (const float4*)(Qn + (size_t)(qBase + qScan) * DQ);
#pragma unroll 2
        for (int j = 0; j < TOPS; j++) {
            const float4* kr = (const float4*)(Kn + (size_t)itop[j] * DQ);
            float s = 0.f;
#pragma unroll 4
            for (int t = 0; t < 72; t++) {
                float4 a = qr[t], b = kr[t];
                s += a.x * b.x; s += a.y * b.y; s += a.z * b.z; s += a.w * b.w;
            }
            cand->v [qScan][span * TOPS + j] = s;
            cand->id[qScan][span * TOPS + j] = itop[j];
        }
    }
    __syncthreads();

    // ---- final top-5 selection (tie -> lower index) ----
    if (tid < 64) {
        int q = tid;
        for (int r = 0; r < 5; r++) {
            float best = -1e30f; int bi = 0x7fffffff; int bj = 0;
            for (int j = 0; j < NCAND; j++) {
                float v = cand->v[q][j]; int id = cand->id[q][j];
                if (v > best || (v == best && id < bi)) { best = v; bi = id; bj = j; }
            }
            tvals[(qBase + q) * 5 + r] = best;
            tidx [(qBase + q) * 5 + r] = bi;
            cand->v[q][bj] = -1e31f;
        }
    }
}

// ---------------------------------------------------------------------------
__global__ void assemble_kernel(const float* __restrict__ x,
                                const float* __restrict__ xT,
                                const float* __restrict__ feat,
                                const float* __restrict__ tvals,
                                const int*   __restrict__ tidx,
                                float* __restrict__ out)
{
    const int tid = threadIdx.x;
    const int pix = blockIdx.x * 4 + (tid >> 6);
    const int c = tid & 63;
    const int Y = pix / Ww, X = pix - Y * Ww;

    float s = 0.f;
#pragma unroll
    for (int r = 1; r < 5; r++) {
        float S = tvals[pix * 5 + r];
        float inner = 0.f;
#pragma unroll
        for (int dy = -1; dy <= 1; dy++) {
            int ly = Y + dy;
            if (ly < 0 || ly >= Hh) continue;
#pragma unroll
            for (int dx = -1; dx <= 1; dx++) {
                int lx = X + dx;
                if (lx < 0 || lx >= Ww) continue;
                int m = tidx[(ly * Ww + lx) * 5 + r];
                int my = m / Ww, mx = m - my * Ww;
                int sy = my - dy, sx = mx - dx;
                if (sy >= 0 && sy < Hh && sx >= 0 && sx < Ww)
                    inner += xT[(sy * Ww + sx) * CIN + c];
            }
        }
        s += S * inner;
    }
    out[c * HW + pix] = feat[c * HW + pix] + x[c * HW + pix] + s * (1.0f / 36.0f);
}

// ---------------------------------------------------------------------------
extern "C" void kernel_launch(void* const* d_in, const int* in_sizes, int n_in,
                              void* d_out, int out_size)
{
    (void)in_sizes; (void)n_in; (void)out_size;
    const float* x  = (const float*)d_in[0];
    const float* W1 = (const float*)d_in[1];
    const float* b1 = (const float*)d_in[2];
    const float* W2 = (const float*)d_in[3];
    const float* b2 = (const float*)d_in[4];
    const float* Wq = (const float*)d_in[5];
    const float* bq = (const float*)d_in[6];
    const float* Wk = (const float*)d_in[7];
    const float* bk = (const float*)d_in[8];
    float* out = (float*)d_out;

    float *t1, *feat, *qb, *kb, *Qn, *Kn, *xT, *tv;
    uint8_t *Qn8, *Kn8;
    int* ti;
    cudaGetSymbolAddress((void**)&t1,   g_t1);
    cudaGetSymbolAddress((void**)&feat, g_feat);
    cudaGetSymbolAddress((void**)&qb,   g_q);
    cudaGetSymbolAddress((void**)&kb,   g_k);
    cudaGetSymbolAddress((void**)&Qn,   g_Qn);
    cudaGetSymbolAddress((void**)&Kn,   g_Kn);
    cudaGetSymbolAddress((void**)&Qn8,  g_Qn8);
    cudaGetSymbolAddress((void**)&Kn8,  g_Kn8);
    cudaGetSymbolAddress((void**)&xT,   g_xT);
    cudaGetSymbolAddress((void**)&tv,   g_tv);
    cudaGetSymbolAddress((void**)&ti,   g_ti);

    cudaFuncSetAttribute(sim_top5_s8,
                         cudaFuncAttributeMaxDynamicSharedMemorySize, SIM_SMEM);

    dim3 cblk(32, 8);
    conv3x3_t<2><<<dim3(3, 6, 16), cblk>>>(x,  W1, b1, t1,   1);
    conv3x3_t<2><<<dim3(3, 6, 16), cblk>>>(t1, W2, b2, feat, 1);
    conv3x3_t<1><<<dim3(3, 12, 8), cblk>>>(x,  Wq, bq, qb,   0);
    conv3x3_t<1><<<dim3(3, 12, 8), cblk>>>(x,  Wk, bk, kb,   0);

    patch_norm_kernel<<<dim3(LQ, 2), DQ>>>(qb, kb, Qn, Qn8, Kn, Kn8);
    transpose_x_kernel<<<(CIN * HW + 255) / 256, 256>>>(x, xT);

    sim_top5_s8<<<144, 256, SIM_SMEM>>>(Kn8, Qn8, Kn, Qn, tv, ti);

    assemble_kernel<<<HW / 4, 256>>>(x, xT, feat, tv, ti, out);
}

// round 17
// speedup vs baseline: 1.1923x; 1.1851x over previous
#include <cuda_runtime.h>
#include <cuda_bf16.h>
#include <cstdint>

// ---------------------------------------------------------------------------
// TransformerV2: conv feature branch + patch-similarity top-5 attention.
// Shapes fixed: B=1, Cin=64, Cq=32, H=W=96, L=9216, D=32*9=288.
// R16: graph-level overlap — feature convs + transpose forked onto a second
//      stream (capture-legal fork/join via events), rejoining before
//      assemble. q+k convs merged into one 576-CTA launch. Numerical path
//      identical to the 860us best (bf16 mma.sync sim + fp32 rescore).
// ---------------------------------------------------------------------------

#define Hh 96
#define Ww 96
#define HW 9216
#define CIN 64
#define CQ  32
#define DQ  288
#define LQ  9216

typedef unsigned long long ull;

// -------------------------- scratch (static, no allocs) --------------------
__device__ float g_t1  [CIN * HW];
__device__ float g_feat[CIN * HW];
__device__ float g_q   [CQ  * HW];
__device__ float g_k   [CQ  * HW];
__device__ float g_Qn  [LQ * DQ];          // fp32 normalized (exact rescore)
__device__ float g_Kn  [LQ * DQ];
__device__ __nv_bfloat16 g_Qnb[LQ * DQ];   // bf16 normalized (for MMA)
__device__ __nv_bfloat16 g_Knb[LQ * DQ];
__device__ float g_xT  [HW * CIN];
__device__ float g_tv  [LQ * 5];
__device__ int   g_ti  [LQ * 5];

// ======================= PTX helpers (compute_103-safe) ====================
__device__ __forceinline__ uint32_t smem_u32(const void* p) {
    uint32_t a;
    asm("{ .reg .u64 t; cvta.to.shared.u64 t, %1; cvt.u32.u64 %0, t; }"
        : "=r"(a) : "l"(p));
    return a;
}
__device__ __forceinline__ void cp16(uint32_t dst, const void* src) {
    asm volatile("cp.async.cg.shared.global [%0], [%1], 16;"
                 :: "r"(dst), "l"(src) : "memory");
}
#define CP_COMMIT() asm volatile("cp.async.commit_group;" ::: "memory")
#define CP_WAIT0()  asm volatile("cp.async.wait_group 0;" ::: "memory")

__device__ __forceinline__ void ldsm4(uint32_t* r, uint32_t addr) {
    asm volatile("ldmatrix.sync.aligned.m8n8.x4.shared.b16 {%0,%1,%2,%3}, [%4];"
                 : "=r"(r[0]), "=r"(r[1]), "=r"(r[2]), "=r"(r[3]) : "r"(addr));
}
__device__ __forceinline__ void mma16816(float* d, const uint32_t* a,
                                         const uint32_t* b) {
    asm volatile(
        "mma.sync.aligned.m16n8k16.row.col.f32.bf16.bf16.f32 "
        "{%0,%1,%2,%3}, {%4,%5,%6,%7}, {%8,%9}, {%0,%1,%2,%3};"
        : "+f"(d[0]), "+f"(d[1]), "+f"(d[2]), "+f"(d[3])
        : "r"(a[0]), "r"(a[1]), "r"(a[2]), "r"(a[3]), "r"(b[0]), "r"(b[1]));
}

// ---------------------------------------------------------------------------
// 3x3 SAME conv, dual weight-set variant (measured R10 body).
// blockIdx.z < nzA -> set A group z, else set B group z-nzA. 4 outs/block.
// ---------------------------------------------------------------------------
template<int RPT>
__global__ void __launch_bounds__(256) conv_dual(
    const float* __restrict__ in,
    const float* __restrict__ wA, const float* __restrict__ bA,
    float* __restrict__ outA,
    const float* __restrict__ wB, const float* __restrict__ bB,
    float* __restrict__ outB,
    int nzA, int doRelu)
{
    constexpr int TH = 8 * RPT;
    constexpr int TL = (TH + 2) * 34;
    constexpr int NP = (TL + 255) / 256;

    __shared__ float tin[2][TH + 2][36];
    __shared__ float wsm[64][36];

    const int tx = threadIdx.x;
    const int ty = threadIdx.y;
    const int tid = ty * 32 + tx;
    const int x0 = blockIdx.x * 32;
    const int y0 = blockIdx.y * TH;
    const int zi = blockIdx.z;
    const bool isA = (zi < nzA);
    const int og = (isA ? zi : zi - nzA) * 4;
    const float* wgt  = isA ? wA : wB;
    const float* bias = isA ? bA : bB;
    float* out        = isA ? outA : outB;

    for (int i = tid; i < 4 * 64 * 9; i += 256) {
        int o = i / 576, rem = i - o * 576, ci = rem / 9, k = rem - ci * 9;
        wsm[ci][o * 9 + k] = wgt[((og + o) * 64 + ci) * 9 + k];
    }

    float pf[NP];
#pragma unroll
    for (int j = 0; j < NP; j++) {
        int i = tid + j * 256;
        float v = 0.f;
        if (i < TL) {
            int r = i / 34, c = i - r * 34;
            int gy = y0 - 1 + r, gx = x0 - 1 + c;
            if (gy >= 0 && gy < Hh && gx >= 0 && gx < Ww)
                v = in[gy * Ww + gx];
        }
        pf[j] = v;
    }

    float acc[4][RPT];
#pragma unroll
    for (int o = 0; o < 4; o++)
#pragma unroll
        for (int rr = 0; rr < RPT; rr++) acc[o][rr] = 0.f;

    for (int ci = 0; ci < 64; ci++) {
        const int buf = ci & 1;
#pragma unroll
        for (int j = 0; j < NP; j++) {
            int i = tid + j * 256;
            if (i < TL) {
                int r = i / 34, c = i - r * 34;
                tin[buf][r][c] = pf[j];
            }
        }
        __syncthreads();

        if (ci < 63) {
            const float* p = in + (ci + 1) * HW;
#pragma unroll
            for (int j = 0; j < NP; j++) {
                int i = tid + j * 256;
                float v = 0.f;
                if (i < TL) {
                    int r = i / 34, c = i - r * 34;
                    int gy = y0 - 1 + r, gx = x0 - 1 + c;
                    if (gy >= 0 && gy < Hh && gx >= 0 && gx < Ww)
                        v = p[gy * Ww + gx];
                }
                pf[j] = v;
            }
        }

        float v[RPT][9];
#pragma unroll
        for (int rr = 0; rr < RPT; rr++) {
            int yl = ty + 8 * rr;
#pragma unroll
            for (int dy = 0; dy < 3; dy++)
#pragma unroll
                for (int dx = 0; dx < 3; dx++)
                    v[rr][dy * 3 + dx] = tin[buf][yl + dy][tx + dx];
        }
#pragma unroll
        for (int o = 0; o < 4; o++) {
            float w9[9];
#pragma unroll
            for (int k = 0; k < 9; k++) w9[k] = wsm[ci][o * 9 + k];
#pragma unroll
            for (int rr = 0; rr < RPT; rr++)
#pragma unroll
                for (int k = 0; k < 9; k++)
                    acc[o][rr] = fmaf(v[rr][k], w9[k], acc[o][rr]);
        }
    }

    const int gx = x0 + tx;
#pragma unroll
    for (int o = 0; o < 4; o++) {
        float b = bias[og + o];
#pragma unroll
        for (int rr = 0; rr < RPT; rr++) {
            int gy = y0 + ty + 8 * rr;
            float r = acc[o][rr] + b;
            if (doRelu) r = fmaxf(r, 0.f);
            out[(og + o) * HW + gy * Ww + gx] = r;
        }
    }
}

// ---------------------------------------------------------------------------
// L2-normalized 3x3 patch vectors, fp32 + bf16 outputs (merged q+k launch).
// ---------------------------------------------------------------------------
__global__ void patch_norm_kernel(
    const float* __restrict__ fq, const float* __restrict__ fk,
    float* __restrict__ vq, __nv_bfloat16* __restrict__ vqb,
    float* __restrict__ vk, __nv_bfloat16* __restrict__ vkb)
{
    const float* f = blockIdx.y ? fk : fq;
    float* vec = blockIdx.y ? vk : vq;
    __nv_bfloat16* vecb = blockIdx.y ? vkb : vqb;

    const int l = blockIdx.x;
    const int y = l / Ww, x = l - y * Ww;
    const int d = threadIdx.x;
    const int c = d / 9, ij = d - c * 9;
    const int dy = ij / 3 - 1, dx = ij % 3 - 1;
    const int yy = y + dy, xx = x + dx;

    float v = 0.f;
    if (yy >= 0 && yy < Hh && xx >= 0 && xx < Ww)
        v = f[c * HW + yy * Ww + xx];

    __shared__ float red[9];
    __shared__ float nrm;
    float s = v * v;
#pragma unroll
    for (int off = 16; off > 0; off >>= 1)
        s += __shfl_down_sync(0xffffffffu, s, off);
    if ((d & 31) == 0) red[d >> 5] = s;
    __syncthreads();
    if (d == 0) {
        float t = 0.f;
#pragma unroll
        for (int i = 0; i < 9; i++) t += red[i];
        nrm = fmaxf(sqrtf(t), 1e-12f);
    }
    __syncthreads();
    float o = v / nrm;
    vec[l * DQ + d]  = o;
    vecb[l * DQ + d] = __float2bfloat16(o);
}

// ---------------------------------------------------------------------------
__global__ void transpose_x_kernel(const float* __restrict__ x,
                                   float* __restrict__ xT)
{
    int i = blockIdx.x * 256 + threadIdx.x;
    if (i < CIN * HW) {
        int p = i >> 6, c = i & 63;
        xT[i] = x[c * HW + p];
    }
}

// ---------------------------------------------------------------------------
// bf16 mma.sync similarity + streaming top-8/span + exact fp32 rescore.
// (R10 kernel verbatim — measured component of the 860us best.)
// ---------------------------------------------------------------------------
#define ASTR   296
#define ABYTES (128 * ASTR * 2)
#define SMB_B  (2 * ABYTES)
#define SMB_SC (SMB_B + 64 * ASTR * 2)
#define SIM_SMEM (SMB_SC + 128 * 66 * 4)

struct SimCand { float v[64][32]; int id[64][32]; };

__global__ void __launch_bounds__(256, 1) sim_top5_mma(
    const __nv_bfloat16* __restrict__ Knb,
    const __nv_bfloat16* __restrict__ Qnb,
    const float* __restrict__ Kn,
    const float* __restrict__ Qn,
    float* __restrict__ tvals,
    int*   __restrict__ tidx)
{
    extern __shared__ __align__(16) char dynsm[];
    const uint32_t smb = smem_u32(dynsm);
    float* scores = (float*)(dynsm + SMB_SC);
    SimCand* cand = (SimCand*)(dynsm + SMB_SC);

    const int tid  = threadIdx.x;
    const int lane = tid & 31;
    const int wid  = tid >> 5;
    const int qBase = blockIdx.x * 64;

    const int wK = (wid & 3) * 32;
    const int wQ = (wid >> 2) * 32;

    const int sRow = tid >> 1, sHalf = tid & 1;

    if (tid < 128) {
        const __nv_bfloat16* src = Qnb + (qBase + sRow) * DQ + sHalf * 144;
        uint32_t dst = smb + SMB_B + sRow * (ASTR * 2) + sHalf * 288;
#pragma unroll
        for (int j = 0; j < 18; j++) cp16(dst + j * 16, src + j * 8);
    }
    {
        const __nv_bfloat16* src = Knb + sRow * DQ + sHalf * 144;
        uint32_t dst = smb + sRow * (ASTR * 2) + sHalf * 288;
#pragma unroll
        for (int j = 0; j < 18; j++) cp16(dst + j * 16, src + j * 8);
    }
    CP_COMMIT();
    CP_WAIT0();
    __syncthreads();

    const uint32_t aOff0 = (uint32_t)(wK + (lane & 15)) * (ASTR * 2)
                         + ((lane >> 4) & 1) * 16;
    const uint32_t aOff1 = aOff0 + 16 * (ASTR * 2);
    const uint32_t bRowCom = ((lane >> 4) & 1) * 8 + (lane & 7);
    const uint32_t bOff0 = smb + SMB_B + (uint32_t)(wQ + bRowCom) * (ASTR * 2)
                         + ((lane >> 3) & 1) * 16;
    const uint32_t bOff1 = bOff0 + 16 * (ASTR * 2);

    float v8[8]; int i8[8];
#pragma unroll
    for (int r = 0; r < 8; r++) { v8[r] = -1e30f; i8[r] = 0; }
    const int qScan = tid & 63, span = tid >> 6;

    for (int kt = 0; kt < 72; kt++) {
        const uint32_t aBuf = smb + (uint32_t)(kt & 1) * ABYTES;

        if (kt < 71) {
            const __nv_bfloat16* src =
                Knb + (size_t)((kt + 1) * 128 + sRow) * DQ + sHalf * 144;
            uint32_t dst = smb + (uint32_t)((kt + 1) & 1) * ABYTES
                         + sRow * (ASTR * 2) + sHalf * 288;
#pragma unroll
            for (int j = 0; j < 18; j++) cp16(dst + j * 16, src + j * 8);
            CP_COMMIT();
        }

        float acc[8][4];
#pragma unroll
        for (int f = 0; f < 8; f++)
#pragma unroll
            for (int e = 0; e < 4; e++) acc[f][e] = 0.f;

#pragma unroll
        for (int ks = 0; ks < 18; ks++) {
            const uint32_t kb = ks * 32;
            uint32_t a0[4], a1[4], b0[4], b1[4];
            ldsm4(a0, aBuf + aOff0 + kb);
            ldsm4(a1, aBuf + aOff1 + kb);
            ldsm4(b0, bOff0 + kb);
            ldsm4(b1, bOff1 + kb);
            mma16816(acc[0], a0, b0);     mma16816(acc[4], a1, b0);
            mma16816(acc[1], a0, b0 + 2); mma16816(acc[5], a1, b0 + 2);
            mma16816(acc[2], a0, b1);     mma16816(acc[6], a1, b1);
            mma16816(acc[3], a0, b1 + 2); mma16816(acc[7], a1, b1 + 2);
        }

#pragma unroll
        for (int mi = 0; mi < 2; mi++)
#pragma unroll
            for (int ni = 0; ni < 4; ni++) {
                const float* d = acc[mi * 4 + ni];
                int row = wK + mi * 16 + (lane >> 2);
                int col = wQ + ni * 8 + (lane & 3) * 2;
                *(float2*)&scores[row * 66 + col] = make_float2(d[0], d[1]);
                *(float2*)&scores[(row + 8) * 66 + col] = make_float2(d[2], d[3]);
            }
        __syncthreads();

        {
            const float* col = scores + (span * 32) * 66 + qScan;
            const int gBase = kt * 128 + span * 32;
            for (int i = 0; i < 32; i++) {
                float v = col[i * 66];
                if (v > v8[7]) {
                    v8[7] = v; i8[7] = gBase + i;
#pragma unroll
                    for (int r = 7; r > 0; r--)
                        if (v8[r] > v8[r - 1]) {
                            float tv = v8[r - 1]; v8[r - 1] = v8[r]; v8[r] = tv;
                            int ti = i8[r - 1]; i8[r - 1] = i8[r]; i8[r] = ti;
                        }
                }
            }
        }
        if (kt < 71) CP_WAIT0();
        __syncthreads();
    }

#pragma unroll
    for (int r = 0; r < 8; r++) {
        cand->v [qScan][span * 8 + r] = v8[r];
        cand->id[qScan][span * 8 + r] = i8[r];
    }
    __syncthreads();

    {
        const float4* qr = (const float4*)(Qn + (size_t)(qBase + qScan) * DQ);
        int ids[8];
#pragma unroll
        for (int j = 0; j < 8; j++) ids[j] = cand->id[qScan][span * 8 + j];
#pragma unroll
        for (int j = 0; j < 8; j++) {
            const float4* kr = (const float4*)(Kn + (size_t)ids[j] * DQ);
            float s = 0.f;
#pragma unroll 4
            for (int t = 0; t < 72; t++) {
                float4 a = qr[t], b = kr[t];
                s += a.x * b.x; s += a.y * b.y; s += a.z * b.z; s += a.w * b.w;
            }
            cand->v[qScan][span * 8 + j] = s;
        }
    }
    __syncthreads();

    if (tid < 64) {
        int q = tid;
        for (int r = 0; r < 5; r++) {
            float best = -1e30f; int bi = 0x7fffffff; int bj = 0;
            for (int j = 0; j < 32; j++) {
                float v = cand->v[q][j]; int id = cand->id[q][j];
                if (v > best || (v == best && id < bi)) { best = v; bi = id; bj = j; }
            }
            tvals[(qBase + q) * 5 + r] = best;
            tidx [(qBase + q) * 5 + r] = bi;
            cand->v[q][bj] = -1e31f;
        }
    }
}

// ---------------------------------------------------------------------------
__global__ void assemble_kernel(const float* __restrict__ x,
                                const float* __restrict__ xT,
                                const float* __restrict__ feat,
                                const float* __restrict__ tvals,
                                const int*   __restrict__ tidx,
                                float* __restrict__ out)
{
    const int tid = threadIdx.x;
    const int pix = blockIdx.x * 4 + (tid >> 6);
    const int c = tid & 63;
    const int Y = pix / Ww, X = pix - Y * Ww;

    float s = 0.f;
#pragma unroll
    for (int r = 1; r < 5; r++) {
        float S = tvals[pix * 5 + r];
        float inner = 0.f;
#pragma unroll
        for (int dy = -1; dy <= 1; dy++) {
            int ly = Y + dy;
            if (ly < 0 || ly >= Hh) continue;
#pragma unroll
            for (int dx = -1; dx <= 1; dx++) {
                int lx = X + dx;
                if (lx < 0 || lx >= Ww) continue;
                int m = tidx[(ly * Ww + lx) * 5 + r];
                int my = m / Ww, mx = m - my * Ww;
                int sy = my - dy, sx = mx - dx;
                if (sy >= 0 && sy < Hh && sx >= 0 && sx < Ww)
                    inner += xT[(sy * Ww + sx) * CIN + c];
            }
        }
        s += S * inner;
    }
    out[c * HW + pix] = feat[c * HW + pix] + x[c * HW + pix] + s * (1.0f / 36.0f);
}

// ---------------------------------------------------------------------------
extern "C" void kernel_launch(void* const* d_in, const int* in_sizes, int n_in,
                              void* d_out, int out_size)
{
    (void)in_sizes; (void)n_in; (void)out_size;
    const float* x  = (const float*)d_in[0];
    const float* W1 = (const float*)d_in[1];
    const float* b1 = (const float*)d_in[2];
    const float* W2 = (const float*)d_in[3];
    const float* b2 = (const float*)d_in[4];
    const float* Wq = (const float*)d_in[5];
    const float* bq = (const float*)d_in[6];
    const float* Wk = (const float*)d_in[7];
    const float* bk = (const float*)d_in[8];
    float* out = (float*)d_out;

    float *t1, *feat, *qb, *kb, *Qn, *Kn, *xT, *tv;
    __nv_bfloat16 *Qnb, *Knb;
    int* ti;
    cudaGetSymbolAddress((void**)&t1,   g_t1);
    cudaGetSymbolAddress((void**)&feat, g_feat);
    cudaGetSymbolAddress((void**)&qb,   g_q);
    cudaGetSymbolAddress((void**)&kb,   g_k);
    cudaGetSymbolAddress((void**)&Qn,   g_Qn);
    cudaGetSymbolAddress((void**)&Kn,   g_Kn);
    cudaGetSymbolAddress((void**)&Qnb,  g_Qnb);
    cudaGetSymbolAddress((void**)&Knb,  g_Knb);
    cudaGetSymbolAddress((void**)&xT,   g_xT);
    cudaGetSymbolAddress((void**)&tv,   g_tv);
    cudaGetSymbolAddress((void**)&ti,   g_ti);

    cudaFuncSetAttribute(sim_top5_mma,
                         cudaFuncAttributeMaxDynamicSharedMemorySize, SIM_SMEM);

    // one-time stream/event setup (host-side resources only; the captured
    // graph and all device work are identical on every call)
    static cudaStream_t sF = nullptr;
    static cudaEvent_t evRoot = nullptr, evFeat = nullptr;
    if (sF == nullptr) {
        cudaStreamCreateWithFlags(&sF, cudaStreamNonBlocking);
        cudaEventCreateWithFlags(&evRoot, cudaEventDisableTiming);
        cudaEventCreateWithFlags(&evFeat, cudaEventDisableTiming);
    }

    dim3 cblk(32, 8);

    // ---- fork: feature chain on sF ----
    cudaEventRecord(evRoot, 0);
    cudaStreamWaitEvent(sF, evRoot, 0);
    conv_dual<2><<<dim3(3, 6, 16), cblk, 0, sF>>>(
        x,  W1, b1, t1,   W1, b1, t1,   16, 1);
    conv_dual<2><<<dim3(3, 6, 16), cblk, 0, sF>>>(
        t1, W2, b2, feat, W2, b2, feat, 16, 1);
    transpose_x_kernel<<<(CIN * HW + 255) / 256, 256, 0, sF>>>(x, xT);
    cudaEventRecord(evFeat, sF);

    // ---- critical chain on the main stream ----
    conv_dual<1><<<dim3(3, 12, 16), cblk>>>(
        x, Wq, bq, qb, Wk, bk, kb, 8, 0);           // merged q+k, 576 CTAs
    patch_norm_kernel<<<dim3(LQ, 2), DQ>>>(qb, kb, Qn, Qnb, Kn, Knb);
    sim_top5_mma<<<144, 256, SIM_SMEM>>>(Knb, Qnb, Kn, Qn, tv, ti);

    // ---- join, then assemble ----
    cudaStreamWaitEvent(0, evFeat, 0);
    assemble_kernel<<<HW / 4, 256>>>(x, xT, feat, tv, ti, out);
}